// round 3
// baseline (speedup 1.0000x reference)
#include <cuda_runtime.h>
#include <math.h>
#include <stdint.h>

#define B 512
#define D 512
#define C 1000
#define M 200
#define KP 50
#define KN 20
#define NROWS (C*KN)              // 20000
#define TEMP 0.07f
#define MARGIN 0.5f
#define BM 64
#define BN 128
#define BK 16
#define NT ((NROWS + BN - 1)/BN)  // 157

typedef unsigned long long ull;

// packed f32x2 FMA (Blackwell native 2xFP32 pipe; PTX-only encoding)
#define FMA_F32X2(d, a, b, c) \
    asm("fma.rn.f32x2 %0, %1, %2, %3;" : "=l"(d) : "l"(a), "l"(b), "l"(c))
#define UNPACK_F32X2(lo, hi, in) \
    asm("mov.b64 {%0, %1}, %2;" : "=r"(lo), "=r"(hi) : "l"(in))

// ---------------- scratch (static device globals; no allocation) ----------------
__device__ float g_f[B*D];        // normalized features
__device__ int   g_rank[B];
__device__ int   g_gsize[B];
__device__ int   g_fidx[B];
__device__ int   g_ov[C*KP];      // override: batch index written into mem[c][k], else -1
__device__ float g_own[B];
__device__ float g_posb[B];
__device__ int   g_cntb[B];
__device__ float g_all [NT*B];    // per-(ntile, b) partials (deterministic reduction)
__device__ float g_hard[NT*B];
__device__ int   g_hcnt[NT*B];

// ---------------- init override table ----------------
__global__ void k_init() {
    int i = blockIdx.x * blockDim.x + threadIdx.x;
    if (i < C*KP) g_ov[i] = -1;
}

// ---------------- L2 normalize rows of features ----------------
__global__ void k_norm(const float* __restrict__ x) {
    int r = blockIdx.x, t = threadIdx.x;
    __shared__ float red[8];
    __shared__ float inv_s;
    const float* row = x + (size_t)r * D;
    float s = 0.f;
    for (int d = t; d < D; d += 256) { float v = row[d]; s = fmaf(v, v, s); }
    for (int o = 16; o; o >>= 1) s += __shfl_down_sync(0xffffffffu, s, o);
    if ((t & 31) == 0) red[t >> 5] = s;
    __syncthreads();
    if (t == 0) {
        float tot = 0.f;
        for (int i = 0; i < 8; i++) tot += red[i];
        inv_s = 1.0f / fmaxf(sqrtf(tot), 1e-12f);
    }
    __syncthreads();
    float inv = inv_s;
    for (int d = t; d < D; d += 256) g_f[(size_t)r * D + d] = row[d] * inv;
}

// ---------------- per-batch bookkeeping: rank, group size, first index, scatter ----------------
__global__ void k_meta(const int* __restrict__ lab, const int* __restrict__ ptr) {
    __shared__ int sl[B];
    int i = threadIdx.x;
    sl[i] = lab[i];
    __syncthreads();
    int li = sl[i];
    int cb = 0, tot = 0, first = B;
    for (int j = 0; j < B; j++) {
        if (sl[j] == li) { tot++; if (j < i) cb++; if (j < first) first = j; }
    }
    g_rank[i] = cb; g_gsize[i] = tot; g_fidx[i] = first;
    int wp = (ptr[li] + cb) % M;
    if (wp < KP) atomicMax(&g_ov[li*KP + wp], i);
}

// ---------------- in-batch positive sums: masked f @ f^T ----------------
__global__ void k_batchpos(const int* __restrict__ lab) {
    int b = blockIdx.x, t = threadIdx.x;
    // fast path: singleton class in batch -> zero contribution
    if (g_gsize[b] <= 1) {
        if (t == 0) { g_posb[b] = 0.f; g_cntb[b] = 0; }
        return;
    }
    __shared__ float fb[D];
    for (int d = t; d < D; d += 256) fb[d] = g_f[(size_t)b*D + d];
    __syncthreads();
    int lb = lab[b], fi = g_fidx[b];
    float s = 0.f; int c = 0;
    for (int j = t; j < B; j += 256) {
        if (lab[j] == lb && g_rank[j] != fi) {
            const float* fj = g_f + (size_t)j * D;
            float d0 = 0.f;
            #pragma unroll 4
            for (int d = 0; d < D; d++) d0 = fmaf(fb[d], fj[d], d0);
            s += d0 / TEMP; c++;
        }
    }
    for (int o = 16; o; o >>= 1) {
        s += __shfl_down_sync(0xffffffffu, s, o);
        c += __shfl_down_sync(0xffffffffu, c, o);
    }
    __shared__ float ss[8]; __shared__ int cs[8];
    int lane = t & 31, w = t >> 5;
    if (!lane) { ss[w] = s; cs[w] = c; }
    __syncthreads();
    if (t == 0) {
        float S = 0.f; int CC = 0;
        for (int i = 0; i < 8; i++) { S += ss[i]; CC += cs[i]; }
        g_posb[b] = S; g_cntb[b] = CC;
    }
}

// ---------------- own-class memory positives: 50 dots per b ----------------
__global__ void k_own(const int* __restrict__ lab, const float* __restrict__ mb) {
    int b = blockIdx.x, t = threadIdx.x;
    int lane = t & 31, w = t >> 5;
    __shared__ float fb[D];
    for (int d = t; d < D; d += 256) fb[d] = g_f[(size_t)b*D + d];
    __syncthreads();
    int c = lab[b];
    float acc = 0.f;
    for (int k = w; k < KP; k += 8) {
        int o = g_ov[c*KP + k];
        const float* row = (o >= 0) ? (g_f + (size_t)o * D)
                                    : (mb + ((size_t)c * M + k) * D);
        float s = 0.f;
        for (int d = lane; d < D; d += 32) s = fmaf(fb[d], row[d], s);
        for (int off = 16; off; off >>= 1) s += __shfl_down_sync(0xffffffffu, s, off);
        if (!lane) acc += s / TEMP;
    }
    __shared__ float ws[8];
    if (!lane) ws[w] = acc;
    __syncthreads();
    if (t == 0) {
        float S = 0.f;
        for (int i = 0; i < 8; i++) S += ws[i];
        g_own[b] = S;
    }
}

// ---------------- main GEMM: sims over (b, c, k<20) with fused neg epilogue ----------------
// FFMA2 version: A stored duplicated ((a,a) pairs) in shared, B pairs read as
// 64-bit lanes, accumulators are f32x2. 16 FFMA2 + 4 LDS.128 per kk-step.
__global__ __launch_bounds__(256) void k_gemm(const int* __restrict__ lab,
                                              const float* __restrict__ mb) {
    __shared__ float As2[BK][BM*2];    // duplicated pairs: [k][m*2 + {0,1}]
    __shared__ float Bs[BK][BN];
    __shared__ const float* bptr[BN];
    __shared__ int ncls[BN];

    int ntile = blockIdx.x, btile = blockIdx.y;
    int n0 = ntile * BN, b0 = btile * BM;
    int tid = threadIdx.x;
    int tx = tid & 15, ty = tid >> 4;

    for (int i = tid; i < BN; i += 256) {
        int n = n0 + i;
        if (n < NROWS) {
            int c = n / KN, k = n - c * KN;
            int o = g_ov[c*KP + k];
            bptr[i] = (o >= 0) ? (g_f + (size_t)o * D)
                               : (mb + ((size_t)c * M + k) * D);
            ncls[i] = c;
        } else {
            bptr[i] = g_f;       // safe dummy; masked in epilogue
            ncls[i] = -1;
        }
    }
    __syncthreads();

    ull acc2[4][4];
    #pragma unroll
    for (int i = 0; i < 4; i++)
        #pragma unroll
        for (int j = 0; j < 4; j++) acc2[i][j] = 0ull;   // (+0.f, +0.f)

    int la_b = tid >> 2;            // 0..63
    int la_k = (tid & 3) * 4;       // 0,4,8,12
    int lb_n = tid >> 1;            // 0..127
    int lb_k = (tid & 1) * 8;       // 0 or 8
    const float* arow = g_f + (size_t)(b0 + la_b) * D + la_k;
    const float* brow = bptr[lb_n] + lb_k;

    for (int k0 = 0; k0 < D; k0 += BK) {
        float4 av  = *(const float4*)(arow + k0);
        float4 bv0 = *(const float4*)(brow + k0);
        float4 bv1 = *(const float4*)(brow + k0 + 4);
        *(float2*)&As2[la_k+0][la_b*2] = make_float2(av.x, av.x);
        *(float2*)&As2[la_k+1][la_b*2] = make_float2(av.y, av.y);
        *(float2*)&As2[la_k+2][la_b*2] = make_float2(av.z, av.z);
        *(float2*)&As2[la_k+3][la_b*2] = make_float2(av.w, av.w);
        Bs[lb_k+0][lb_n] = bv0.x; Bs[lb_k+1][lb_n] = bv0.y;
        Bs[lb_k+2][lb_n] = bv0.z; Bs[lb_k+3][lb_n] = bv0.w;
        Bs[lb_k+4][lb_n] = bv1.x; Bs[lb_k+5][lb_n] = bv1.y;
        Bs[lb_k+6][lb_n] = bv1.z; Bs[lb_k+7][lb_n] = bv1.w;
        __syncthreads();
        #pragma unroll
        for (int kk = 0; kk < BK; kk++) {
            // duplicated A pairs: (a,a) for m = ty*4 .. ty*4+3
            ulonglong2 a01 = *(const ulonglong2*)&As2[kk][ty*8];
            ulonglong2 a23 = *(const ulonglong2*)&As2[kk][ty*8 + 4];
            // B pairs: n = tx*8 + {0,1},{2,3},{4,5},{6,7}
            ulonglong2 b01 = *(const ulonglong2*)&Bs[kk][tx*8];
            ulonglong2 b23 = *(const ulonglong2*)&Bs[kk][tx*8 + 4];
            ull ar[4] = {a01.x, a01.y, a23.x, a23.y};
            ull br[4] = {b01.x, b01.y, b23.x, b23.y};
            #pragma unroll
            for (int i = 0; i < 4; i++)
                #pragma unroll
                for (int j = 0; j < 4; j++)
                    FMA_F32X2(acc2[i][j], ar[i], br[j], acc2[i][j]);
        }
        __syncthreads();
    }

    // epilogue: per-b hard/all sums over this n-tile, reduced across tx (width 16)
    int blab[4];
    #pragma unroll
    for (int i = 0; i < 4; i++) blab[i] = lab[b0 + ty*4 + i];

    #pragma unroll
    for (int i = 0; i < 4; i++) {
        float alls = 0.f, hards = 0.f; int hc = 0;
        #pragma unroll
        for (int j = 0; j < 4; j++) {
            uint32_t lo_u, hi_u;
            UNPACK_F32X2(lo_u, hi_u, acc2[i][j]);
            float v[2] = { __uint_as_float(lo_u), __uint_as_float(hi_u) };
            #pragma unroll
            for (int h = 0; h < 2; h++) {
                int idx = tx*8 + 2*j + h;
                int c = ncls[idx];
                if (c >= 0 && c != blab[i]) {
                    float sim = v[h] / TEMP;
                    alls += sim;
                    if (sim > MARGIN) { hards += sim; hc++; }
                }
            }
        }
        for (int off = 8; off; off >>= 1) {
            alls  += __shfl_down_sync(0xffffffffu, alls,  off, 16);
            hards += __shfl_down_sync(0xffffffffu, hards, off, 16);
            hc    += __shfl_down_sync(0xffffffffu, hc,    off, 16);
        }
        if (tx == 0) {
            int gb = b0 + ty*4 + i;
            g_all [ntile*B + gb] = alls;
            g_hard[ntile*B + gb] = hards;
            g_hcnt[ntile*B + gb] = hc;
        }
    }
}

// ---------------- finalize: combine, per-b loss, mean ----------------
__global__ void k_final(float* __restrict__ out) {
    int b = threadIdx.x;
    float alls = 0.f, hards = 0.f; int hc = 0;
    for (int t = 0; t < NT; t++) {
        alls  += g_all [t*B + b];
        hards += g_hard[t*B + b];
        hc    += g_hcnt[t*B + b];
    }
    float pos_sum = g_posb[b] + g_own[b];
    float pos_cnt = (float)(g_cntb[b] + KP);
    float pos_loss = -pos_sum / pos_cnt;
    float neg_loss = (hc > 0) ? (hards / (float)(hc > 1 ? hc : 1))
                              : (alls / (float)((C-1) * KN));
    __shared__ float sm[B];
    sm[b] = pos_loss + neg_loss;
    __syncthreads();
    for (int s = 256; s; s >>= 1) {
        if (b < s) sm[b] += sm[b + s];
        __syncthreads();
    }
    if (b == 0) out[0] = sm[0] / (float)B;
}

// ---------------- launch ----------------
extern "C" void kernel_launch(void* const* d_in, const int* in_sizes, int n_in,
                              void* d_out, int out_size) {
    const float* features   = (const float*)d_in[0];
    const int*   labels     = (const int*)  d_in[1];
    const float* memorybank = (const float*)d_in[2];
    const int*   memoryptr  = (const int*)  d_in[3];
    float* out = (float*)d_out;

    k_init    <<<(C*KP + 255)/256, 256>>>();
    k_norm    <<<B, 256>>>(features);
    k_meta    <<<1, B>>>(labels, memoryptr);
    k_batchpos<<<B, 256>>>(labels);
    k_own     <<<B, 256>>>(labels, memorybank);
    k_gemm    <<<dim3(NT, B/BM), 256>>>(labels, memorybank);
    k_final   <<<1, B>>>(out);
}

// round 11
// speedup vs baseline: 3.7452x; 3.7452x over previous
#include <cuda_runtime.h>
#include <math.h>
#include <stdint.h>

#define B 512
#define D 512
#define C 1000
#define M 200
#define KP 50
#define KN 20
#define NROWS (C*KN)              // 20000
#define TEMP 0.07f
#define MARGIN 0.5f
#define TM 128
#define TN 128
#define BK 32
#define NCH (D/BK)                // 16
#define NT ((NROWS + TN - 1)/TN)  // 157
#define NPAD (NT*TN)              // 20096
#define RS 36                     // smem row stride in floats (conflict-free)
#define STAGE (TM*RS*4)           // 18432 bytes per stage
#define DYN_BYTES (4*STAGE)       // A0 A1 B0 B1

// ---------------- PTX helpers ----------------
__device__ __forceinline__ uint32_t smem_u32(const void* p) {
    uint32_t a;
    asm("{ .reg .u64 t; cvta.to.shared.u64 t, %1; cvt.u32.u64 %0, t; }" : "=r"(a) : "l"(p));
    return a;
}
__device__ __forceinline__ uint32_t to_tf32(float v) {
    uint32_t o;
    asm("cvt.rna.tf32.f32 %0, %1;" : "=r"(o) : "f"(v));
    return o;
}
#define CP_ASYNC16(dst, src) \
    asm volatile("cp.async.cg.shared.global [%0], [%1], 16;" :: "r"(dst), "l"(src))
#define CP_COMMIT() asm volatile("cp.async.commit_group;" ::: "memory")
#define CP_WAIT1()  asm volatile("cp.async.wait_group 1;" ::: "memory")
#define CP_WAIT0()  asm volatile("cp.async.wait_group 0;" ::: "memory")

__device__ __forceinline__ void mma_tf32(float* d, const uint32_t* a, const uint32_t* b) {
    asm volatile(
        "mma.sync.aligned.m16n8k8.row.col.f32.tf32.tf32.f32 "
        "{%0,%1,%2,%3}, {%4,%5,%6,%7}, {%8,%9}, {%0,%1,%2,%3};"
        : "+f"(d[0]), "+f"(d[1]), "+f"(d[2]), "+f"(d[3])
        : "r"(a[0]), "r"(a[1]), "r"(a[2]), "r"(a[3]), "r"(b[0]), "r"(b[1]));
}

// ---------------- scratch ----------------
__device__ float    g_f[B*D];
__device__ uint32_t g_atf[B*D];               // tf32 bits, contiguous
__device__ uint32_t g_btf[(size_t)NPAD*D];    // tf32 bits, gather-resolved
__device__ int   g_rank[B];
__device__ int   g_gsize[B];
__device__ int   g_fidx[B];
__device__ int   g_ov[C*KP];
__device__ float g_own[B];
__device__ float g_posb[B];
__device__ int   g_cntb[B];
__device__ float g_all [NT*B];
__device__ float g_hard[NT*B];
__device__ int   g_hcnt[NT*B];

// ---------------- init ----------------
__global__ void k_init() {
    int i = blockIdx.x * blockDim.x + threadIdx.x;
    if (i < C*KP) g_ov[i] = -1;
}

// ---------------- normalize ----------------
__global__ void k_norm(const float* __restrict__ x) {
    int r = blockIdx.x, t = threadIdx.x;
    __shared__ float red[8];
    __shared__ float inv_s;
    const float* row = x + (size_t)r * D;
    float s = 0.f;
    for (int d = t; d < D; d += 256) { float v = row[d]; s = fmaf(v, v, s); }
    for (int o = 16; o; o >>= 1) s += __shfl_down_sync(0xffffffffu, s, o);
    if ((t & 31) == 0) red[t >> 5] = s;
    __syncthreads();
    if (t == 0) {
        float tot = 0.f;
        for (int i = 0; i < 8; i++) tot += red[i];
        inv_s = 1.0f / fmaxf(sqrtf(tot), 1e-12f);
    }
    __syncthreads();
    float inv = inv_s;
    for (int d = t; d < D; d += 256) g_f[(size_t)r * D + d] = row[d] * inv;
}

// ---------------- meta ----------------
__global__ void k_meta(const int* __restrict__ lab, const int* __restrict__ ptr) {
    __shared__ int sl[B];
    int i = threadIdx.x;
    sl[i] = lab[i];
    __syncthreads();
    int li = sl[i];
    int cb = 0, tot = 0, first = B;
    for (int j = 0; j < B; j++) {
        if (sl[j] == li) { tot++; if (j < i) cb++; if (j < first) first = j; }
    }
    g_rank[i] = cb; g_gsize[i] = tot; g_fidx[i] = first;
    int wp = (ptr[li] + cb) % M;
    if (wp < KP) atomicMax(&g_ov[li*KP + wp], i);
}

// ---------------- prep A: tf32-round normalized features ----------------
__global__ void k_prepA() {
    int r = blockIdx.x, t = threadIdx.x;       // 512 blocks x 128 thr
    float4 v = *(const float4*)(g_f + (size_t)r*D + t*4);
    uint4 o = make_uint4(to_tf32(v.x), to_tf32(v.y), to_tf32(v.z), to_tf32(v.w));
    *(uint4*)(g_atf + (size_t)r*D + t*4) = o;
}

// ---------------- prep B: resolve gather, tf32-round ----------------
__global__ void k_prepB(const float* __restrict__ mb) {
    int n = blockIdx.x, t = threadIdx.x;       // 20096 blocks x 128 thr
    uint32_t* dst = g_btf + (size_t)n*D + t*4;
    if (n >= NROWS) {
        *(uint4*)dst = make_uint4(0u, 0u, 0u, 0u);
        return;
    }
    int c = n / KN, k = n - c*KN;
    int o = g_ov[c*KP + k];
    const float* src = (o >= 0) ? (g_f + (size_t)o*D) : (mb + ((size_t)c*M + k)*D);
    float4 v = *(const float4*)(src + t*4);
    uint4 ot = make_uint4(to_tf32(v.x), to_tf32(v.y), to_tf32(v.z), to_tf32(v.w));
    *(uint4*)dst = ot;
}

// ---------------- in-batch positives (warp-per-j) ----------------
__global__ void k_batchpos(const int* __restrict__ lab) {
    int b = blockIdx.x, t = threadIdx.x, w = t >> 5, lid = t & 31;
    if (g_gsize[b] <= 1) {
        if (t == 0) { g_posb[b] = 0.f; g_cntb[b] = 0; }
        return;
    }
    __shared__ float fb[D];
    __shared__ int sl[B];
    for (int d = t; d < D; d += 256) fb[d] = g_f[(size_t)b*D + d];
    for (int j = t; j < B; j += 256) sl[j] = lab[j];
    __syncthreads();
    int lb = lab[b], fi = g_fidx[b];
    float s = 0.f; int c = 0;
    for (int j = w; j < B; j += 8) {
        if (sl[j] == lb && g_rank[j] != fi) {
            const float* fj = g_f + (size_t)j * D;
            float d0 = 0.f;
            for (int d = lid; d < D; d += 32) d0 = fmaf(fb[d], fj[d], d0);
            for (int o = 16; o; o >>= 1) d0 += __shfl_down_sync(0xffffffffu, d0, o);
            if (!lid) { s += d0 / TEMP; c++; }
        }
    }
    __shared__ float ss[8]; __shared__ int cs[8];
    if (!lid) { ss[w] = s; cs[w] = c; }
    __syncthreads();
    if (t == 0) {
        float S = 0.f; int CC = 0;
        for (int i = 0; i < 8; i++) { S += ss[i]; CC += cs[i]; }
        g_posb[b] = S; g_cntb[b] = CC;
    }
}

// ---------------- own-class positives ----------------
__global__ void k_own(const int* __restrict__ lab, const float* __restrict__ mb) {
    int b = blockIdx.x, t = threadIdx.x;
    int lane = t & 31, w = t >> 5;
    __shared__ float fb[D];
    for (int d = t; d < D; d += 256) fb[d] = g_f[(size_t)b*D + d];
    __syncthreads();
    int c = lab[b];
    float acc = 0.f;
    for (int k = w; k < KP; k += 8) {
        int o = g_ov[c*KP + k];
        const float* row = (o >= 0) ? (g_f + (size_t)o * D)
                                    : (mb + ((size_t)c * M + k) * D);
        float s = 0.f;
        for (int d = lane; d < D; d += 32) s = fmaf(fb[d], row[d], s);
        for (int off = 16; off; off >>= 1) s += __shfl_down_sync(0xffffffffu, s, off);
        if (!lane) acc += s / TEMP;
    }
    __shared__ float ws[8];
    if (!lane) ws[w] = acc;
    __syncthreads();
    if (t == 0) {
        float S = 0.f;
        for (int i = 0; i < 8; i++) S += ws[i];
        g_own[b] = S;
    }
}

// ---------------- main GEMM: mma.sync tf32, cp.async double-buffer ----------------
__global__ __launch_bounds__(256) void k_gemm(const int* __restrict__ lab) {
    extern __shared__ char dsm[];
    __shared__ int ncls[TN];
    __shared__ int slab[TM];
    __shared__ float sh_all[4][TM];
    __shared__ float sh_hard[4][TM];
    __shared__ int   sh_hc[4][TM];

    int tid = threadIdx.x, wid = tid >> 5, lid = tid & 31;
    int g = lid >> 2, tig = lid & 3;
    int warp_m = wid & 1, warp_n = wid >> 1;
    int ntile = blockIdx.x, btile = blockIdx.y;
    int n0 = ntile * TN, b0 = btile * TM;

    uint32_t sbase = smem_u32(dsm);

    for (int i = tid; i < TN; i += 256) {
        int n = n0 + i;
        ncls[i] = (n < NROWS) ? (n / KN) : -1;
    }
    for (int i = tid; i < TM; i += 256) slab[i] = lab[b0 + i];

    float d[4][4][4];
    #pragma unroll
    for (int mt = 0; mt < 4; mt++)
        #pragma unroll
        for (int nt = 0; nt < 4; nt++)
            #pragma unroll
            for (int e = 0; e < 4; e++) d[mt][nt][e] = 0.f;

    // per-thread cp.async assignments: 4 iters, each fills one 16B chunk of A and B
    int cp_r[4], cp_c[4];
    #pragma unroll
    for (int it = 0; it < 4; it++) { int i = tid + it*256; cp_r[it] = i >> 3; cp_c[it] = i & 7; }

    // issue stage for chunk ch into buffer q
    #define ISSUE(ch, q) do { \
        uint32_t abase_ = sbase + (q)*STAGE; \
        uint32_t bbase_ = sbase + 2*STAGE + (q)*STAGE; \
        int kb_ = (ch)*BK; \
        _Pragma("unroll") \
        for (int it = 0; it < 4; it++) { \
            int r_ = cp_r[it], c_ = cp_c[it]; \
            CP_ASYNC16(abase_ + (uint32_t)(r_*RS*4 + c_*16), \
                       g_atf + (size_t)(b0 + r_)*D + kb_ + c_*4); \
            CP_ASYNC16(bbase_ + (uint32_t)(r_*RS*4 + c_*16), \
                       g_btf + (size_t)(n0 + r_)*D + kb_ + c_*4); \
        } \
        CP_COMMIT(); \
    } while (0)

    ISSUE(0, 0);

    const uint32_t* Asm = (const uint32_t*)dsm;
    int abase_row = warp_m*64 + g;          // + mt*16 (+8)
    int bbase_row = warp_n*32 + g;          // + nt*8

    for (int ch = 0; ch < NCH; ch++) {
        if (ch + 1 < NCH) { ISSUE(ch + 1, (ch + 1) & 1); CP_WAIT1(); }
        else              { CP_WAIT0(); }
        __syncthreads();

        int p = ch & 1;
        const uint32_t* As = Asm + p*(STAGE/4);
        const uint32_t* Bs = Asm + 2*(STAGE/4) + p*(STAGE/4);

        #pragma unroll
        for (int s = 0; s < 4; s++) {
            int k0 = s * 8;
            uint32_t a[4][4], b[4][2];
            #pragma unroll
            for (int mt = 0; mt < 4; mt++) {
                int r = (abase_row + mt*16) * RS + k0 + tig;
                a[mt][0] = As[r];
                a[mt][1] = As[r + 8*RS];
                a[mt][2] = As[r + 4];
                a[mt][3] = As[r + 8*RS + 4];
            }
            #pragma unroll
            for (int nt = 0; nt < 4; nt++) {
                int r = (bbase_row + nt*8) * RS + k0 + tig;
                b[nt][0] = Bs[r];
                b[nt][1] = Bs[r + 4];
            }
            #pragma unroll
            for (int mt = 0; mt < 4; mt++)
                #pragma unroll
                for (int nt = 0; nt < 4; nt++)
                    mma_tf32(d[mt][nt], a[mt], b[nt]);
        }
        __syncthreads();
    }
    #undef ISSUE

    // fused negative epilogue
    #pragma unroll
    for (int mt = 0; mt < 4; mt++) {
        #pragma unroll
        for (int h = 0; h < 2; h++) {
            int row = warp_m*64 + mt*16 + h*8 + g;
            int blb = slab[row];
            float alls = 0.f, hards = 0.f; int hc = 0;
            #pragma unroll
            for (int nt = 0; nt < 4; nt++) {
                #pragma unroll
                for (int e = 0; e < 2; e++) {
                    int col = warp_n*32 + nt*8 + tig*2 + e;
                    int c = ncls[col];
                    if (c >= 0 && c != blb) {
                        float sim = d[mt][nt][h*2 + e] * (1.0f / TEMP);
                        alls += sim;
                        if (sim > MARGIN) { hards += sim; hc++; }
                    }
                }
            }
            alls  += __shfl_down_sync(0xffffffffu, alls,  2, 4);
            alls  += __shfl_down_sync(0xffffffffu, alls,  1, 4);
            hards += __shfl_down_sync(0xffffffffu, hards, 2, 4);
            hards += __shfl_down_sync(0xffffffffu, hards, 1, 4);
            hc    += __shfl_down_sync(0xffffffffu, hc,    2, 4);
            hc    += __shfl_down_sync(0xffffffffu, hc,    1, 4);
            if (tig == 0) {
                sh_all [warp_n][row] = alls;
                sh_hard[warp_n][row] = hards;
                sh_hc  [warp_n][row] = hc;
            }
        }
    }
    __syncthreads();
    if (tid < TM) {
        float A4 = 0.f, H4 = 0.f; int C4 = 0;
        #pragma unroll
        for (int wn = 0; wn < 4; wn++) {
            A4 += sh_all[wn][tid]; H4 += sh_hard[wn][tid]; C4 += sh_hc[wn][tid];
        }
        int gb = b0 + tid;
        g_all [ntile*B + gb] = A4;
        g_hard[ntile*B + gb] = H4;
        g_hcnt[ntile*B + gb] = C4;
    }
}

// ---------------- finalize ----------------
__global__ void k_final(float* __restrict__ out) {
    int b = threadIdx.x;
    float alls = 0.f, hards = 0.f; int hc = 0;
    for (int t = 0; t < NT; t++) {
        alls  += g_all [t*B + b];
        hards += g_hard[t*B + b];
        hc    += g_hcnt[t*B + b];
    }
    float pos_sum = g_posb[b] + g_own[b];
    float pos_cnt = (float)(g_cntb[b] + KP);
    float pos_loss = -pos_sum / pos_cnt;
    float neg_loss = (hc > 0) ? (hards / (float)(hc > 1 ? hc : 1))
                              : (alls / (float)((C-1) * KN));
    __shared__ float sm[B];
    sm[b] = pos_loss + neg_loss;
    __syncthreads();
    for (int s = 256; s; s >>= 1) {
        if (b < s) sm[b] += sm[b + s];
        __syncthreads();
    }
    if (b == 0) out[0] = sm[0] / (float)B;
}

// ---------------- launch ----------------
extern "C" void kernel_launch(void* const* d_in, const int* in_sizes, int n_in,
                              void* d_out, int out_size) {
    const float* features   = (const float*)d_in[0];
    const int*   labels     = (const int*)  d_in[1];
    const float* memorybank = (const float*)d_in[2];
    const int*   memoryptr  = (const int*)  d_in[3];
    float* out = (float*)d_out;

    static int configured = 0;
    if (!configured) {
        cudaFuncSetAttribute(k_gemm, cudaFuncAttributeMaxDynamicSharedMemorySize, DYN_BYTES);
        configured = 1;
    }

    k_init    <<<(C*KP + 255)/256, 256>>>();
    k_norm    <<<B, 256>>>(features);
    k_meta    <<<1, B>>>(labels, memoryptr);
    k_prepA   <<<B, 128>>>();
    k_prepB   <<<NPAD, 128>>>(memorybank);
    k_batchpos<<<B, 256>>>(labels);
    k_own     <<<B, 256>>>(labels, memorybank);
    k_gemm    <<<dim3(NT, B/TM), 256, DYN_BYTES>>>(labels);
    k_final   <<<1, B>>>(out);
}

// round 14
// speedup vs baseline: 5.1557x; 1.3766x over previous
#include <cuda_runtime.h>
#include <cuda_fp16.h>
#include <math.h>
#include <stdint.h>

#define B 512
#define D 512
#define C 1000
#define M 200
#define KP 50
#define KN 20
#define NROWS (C*KN)              // 20000
#define TEMP 0.07f
#define MARGIN 0.5f
#define TM 128
#define TN 128
#define BK 64                     // halves per chunk (128B rows)
#define NCH (D/BK)                // 8
#define NT ((NROWS + TN - 1)/TN)  // 157
#define NPAD (NT*TN)              // 20096
#define STAGE (TM*128)            // 16384 bytes per stage (128 rows x 128B)
#define DYN_BYTES (4*STAGE)       // A0 A1 B0 B1 = 64KB

// ---------------- PTX helpers ----------------
__device__ __forceinline__ uint32_t smem_u32(const void* p) {
    uint32_t a;
    asm("{ .reg .u64 t; cvta.to.shared.u64 t, %1; cvt.u32.u64 %0, t; }" : "=r"(a) : "l"(p));
    return a;
}
#define CP_ASYNC16(dst, src) \
    asm volatile("cp.async.cg.shared.global [%0], [%1], 16;" :: "r"(dst), "l"(src))
#define CP_COMMIT() asm volatile("cp.async.commit_group;" ::: "memory")
#define CP_WAIT1()  asm volatile("cp.async.wait_group 1;" ::: "memory")
#define CP_WAIT0()  asm volatile("cp.async.wait_group 0;" ::: "memory")

#define LDSM4(r0, r1, r2, r3, addr) \
    asm volatile("ldmatrix.sync.aligned.m8n8.x4.shared.b16 {%0,%1,%2,%3}, [%4];" \
        : "=r"(r0), "=r"(r1), "=r"(r2), "=r"(r3) : "r"(addr))

__device__ __forceinline__ void mma_f16(float* d, const uint32_t* a, uint32_t b0, uint32_t b1) {
    asm volatile(
        "mma.sync.aligned.m16n8k16.row.col.f32.f16.f16.f32 "
        "{%0,%1,%2,%3}, {%4,%5,%6,%7}, {%8,%9}, {%0,%1,%2,%3};"
        : "+f"(d[0]), "+f"(d[1]), "+f"(d[2]), "+f"(d[3])
        : "r"(a[0]), "r"(a[1]), "r"(a[2]), "r"(a[3]), "r"(b0), "r"(b1));
}

// ---------------- scratch ----------------
__device__ float  g_f[B*D];                  // normalized features (fp32, exact paths)
__device__ __half g_ah[B*D];                 // fp16 A
__device__ __half g_bh[(size_t)NPAD*D];      // fp16 B, gather-resolved
__device__ int   g_rank[B];
__device__ int   g_gsize[B];
__device__ int   g_fidx[B];
__device__ int   g_ov[C*KP];
__device__ float g_own[B];
__device__ float g_posb[B];
__device__ int   g_cntb[B];
__device__ float g_all [NT*B];
__device__ float g_hard[NT*B];
__device__ int   g_hcnt[NT*B];

// ---------------- normalize (+ emit fp16 A) ----------------
__global__ void k_norm(const float* __restrict__ x) {
    int r = blockIdx.x, t = threadIdx.x;
    __shared__ float red[8];
    __shared__ float inv_s;
    const float* row = x + (size_t)r * D;
    float s = 0.f;
    for (int d = t; d < D; d += 256) { float v = row[d]; s = fmaf(v, v, s); }
    for (int o = 16; o; o >>= 1) s += __shfl_down_sync(0xffffffffu, s, o);
    if ((t & 31) == 0) red[t >> 5] = s;
    __syncthreads();
    if (t == 0) {
        float tot = 0.f;
        for (int i = 0; i < 8; i++) tot += red[i];
        inv_s = 1.0f / fmaxf(sqrtf(tot), 1e-12f);
    }
    __syncthreads();
    float inv = inv_s;
    for (int d = t; d < D; d += 256) {
        float v = row[d] * inv;
        g_f[(size_t)r * D + d] = v;
        g_ah[(size_t)r * D + d] = __float2half_rn(v);
    }
}

// ---------------- meta (init override table + rank/group/first + scatter) ----------------
__global__ void k_meta(const int* __restrict__ lab, const int* __restrict__ ptr) {
    __shared__ int sl[B];
    int i = threadIdx.x;
    for (int j = i; j < C*KP; j += B) g_ov[j] = -1;
    sl[i] = lab[i];
    __syncthreads();
    int li = sl[i];
    int cb = 0, tot = 0, first = B;
    for (int j = 0; j < B; j++) {
        if (sl[j] == li) { tot++; if (j < i) cb++; if (j < first) first = j; }
    }
    g_rank[i] = cb; g_gsize[i] = tot; g_fidx[i] = first;
    int wp = (ptr[li] + cb) % M;
    if (wp < KP) atomicMax(&g_ov[li*KP + wp], i);
}

// ---------------- prep B: resolve gather, fp16-round ----------------
__global__ void k_prepB(const float* __restrict__ mb) {
    int n = blockIdx.x, t = threadIdx.x;       // NPAD blocks x 128 thr, 4 elems each
    __half* dst = g_bh + (size_t)n*D + t*4;
    if (n >= NROWS) {
        *(uint2*)dst = make_uint2(0u, 0u);
        return;
    }
    int c = n / KN, k = n - c*KN;
    int o = g_ov[c*KP + k];
    const float* src = (o >= 0) ? (g_f + (size_t)o*D) : (mb + ((size_t)c*M + k)*D);
    float4 v = *(const float4*)(src + t*4);
    __half2 h01 = __floats2half2_rn(v.x, v.y);
    __half2 h23 = __floats2half2_rn(v.z, v.w);
    uint2 out;
    out.x = *(uint32_t*)&h01;
    out.y = *(uint32_t*)&h23;
    *(uint2*)dst = out;
}

// ---------------- in-batch positives (warp-per-j, exact fp32) ----------------
__global__ void k_batchpos(const int* __restrict__ lab) {
    int b = blockIdx.x, t = threadIdx.x, w = t >> 5, lid = t & 31;
    if (g_gsize[b] <= 1) {
        if (t == 0) { g_posb[b] = 0.f; g_cntb[b] = 0; }
        return;
    }
    __shared__ float fb[D];
    __shared__ int sl[B];
    for (int d = t; d < D; d += 256) fb[d] = g_f[(size_t)b*D + d];
    for (int j = t; j < B; j += 256) sl[j] = lab[j];
    __syncthreads();
    int lb = lab[b], fi = g_fidx[b];
    float s = 0.f; int c = 0;
    for (int j = w; j < B; j += 8) {
        if (sl[j] == lb && g_rank[j] != fi) {
            const float* fj = g_f + (size_t)j * D;
            float d0 = 0.f;
            for (int d = lid; d < D; d += 32) d0 = fmaf(fb[d], fj[d], d0);
            for (int o = 16; o; o >>= 1) d0 += __shfl_down_sync(0xffffffffu, d0, o);
            if (!lid) { s += d0 / TEMP; c++; }
        }
    }
    __shared__ float ss[8]; __shared__ int cs[8];
    if (!lid) { ss[w] = s; cs[w] = c; }
    __syncthreads();
    if (t == 0) {
        float S = 0.f; int CC = 0;
        for (int i = 0; i < 8; i++) { S += ss[i]; CC += cs[i]; }
        g_posb[b] = S; g_cntb[b] = CC;
    }
}

// ---------------- own-class positives (exact fp32) ----------------
__global__ void k_own(const int* __restrict__ lab, const float* __restrict__ mb) {
    int b = blockIdx.x, t = threadIdx.x;
    int lane = t & 31, w = t >> 5;
    __shared__ float fb[D];
    for (int d = t; d < D; d += 256) fb[d] = g_f[(size_t)b*D + d];
    __syncthreads();
    int c = lab[b];
    float acc = 0.f;
    for (int k = w; k < KP; k += 8) {
        int o = g_ov[c*KP + k];
        const float* row = (o >= 0) ? (g_f + (size_t)o * D)
                                    : (mb + ((size_t)c * M + k) * D);
        float s = 0.f;
        for (int d = lane; d < D; d += 32) s = fmaf(fb[d], row[d], s);
        for (int off = 16; off; off >>= 1) s += __shfl_down_sync(0xffffffffu, s, off);
        if (!lane) acc += s / TEMP;
    }
    __shared__ float ws[8];
    if (!lane) ws[w] = acc;
    __syncthreads();
    if (t == 0) {
        float S = 0.f;
        for (int i = 0; i < 8; i++) S += ws[i];
        g_own[b] = S;
    }
}

// ---------------- main GEMM: fp16 mma.sync m16n8k16 + ldmatrix, cp.async DB ----------------
__global__ __launch_bounds__(256) void k_gemm(const int* __restrict__ lab) {
    extern __shared__ char dsm[];
    __shared__ int ncls[TN];
    __shared__ int slab[TM];
    __shared__ float sh_all[4][TM];
    __shared__ float sh_hard[4][TM];
    __shared__ int   sh_hc[4][TM];

    int tid = threadIdx.x, wid = tid >> 5, lid = tid & 31;
    int g = lid >> 2, tig = lid & 3;
    int warp_m = wid & 1, warp_n = wid >> 1;
    int ntile = blockIdx.x, btile = blockIdx.y;
    int n0 = ntile * TN, b0 = btile * TM;

    uint32_t sbase = smem_u32(dsm);

    for (int i = tid; i < TN; i += 256) {
        int n = n0 + i;
        ncls[i] = (n < NROWS) ? (n / KN) : -1;
    }
    for (int i = tid; i < TM; i += 256) slab[i] = lab[b0 + i];

    float d[4][4][4];
    #pragma unroll
    for (int mt = 0; mt < 4; mt++)
        #pragma unroll
        for (int nt = 0; nt < 4; nt++)
            #pragma unroll
            for (int e = 0; e < 4; e++) d[mt][nt][e] = 0.f;

    // cp.async assignments: i = tid + it*256; row = i>>1 wait: per stage per matrix
    // 128 rows x 8 chunks(16B) = 1024 chunks; 256 thr x 4 it.
    int cp_r[4], cp_c[4];
    #pragma unroll
    for (int it = 0; it < 4; it++) { int i = tid + it*256; cp_r[it] = i >> 3; cp_c[it] = i & 7; }

    #define ISSUE(ch, q) do { \
        uint32_t abase_ = sbase + (q)*STAGE; \
        uint32_t bbase_ = sbase + 2*STAGE + (q)*STAGE; \
        int kb_ = (ch)*BK; \
        _Pragma("unroll") \
        for (int it = 0; it < 4; it++) { \
            int r_ = cp_r[it], c_ = cp_c[it]; \
            int sc_ = c_ ^ (r_ & 7); \
            CP_ASYNC16(abase_ + (uint32_t)(r_*128 + sc_*16), \
                       g_ah + (size_t)(b0 + r_)*D + kb_ + c_*8); \
            CP_ASYNC16(bbase_ + (uint32_t)(r_*128 + sc_*16), \
                       g_bh + (size_t)(n0 + r_)*D + kb_ + c_*8); \
        } \
        CP_COMMIT(); \
    } while (0)

    ISSUE(0, 0);

    // ldmatrix lane geometry
    int xr = lid & 7;
    int jrow = (lid >> 3) & 1;
    int hh = lid >> 4;
    uint32_t aoff[4], boff[2];
    #pragma unroll
    for (int mt = 0; mt < 4; mt++)
        aoff[mt] = (uint32_t)((warp_m*64 + mt*16 + jrow*8 + xr) * 128);
    #pragma unroll
    for (int np = 0; np < 2; np++)
        boff[np] = (uint32_t)((warp_n*32 + np*16 + jrow*8 + xr) * 128);

    for (int ch = 0; ch < NCH; ch++) {
        if (ch + 1 < NCH) { ISSUE(ch + 1, (ch + 1) & 1); CP_WAIT1(); }
        else              { CP_WAIT0(); }
        __syncthreads();

        int p = ch & 1;
        uint32_t sA = sbase + p*STAGE;
        uint32_t sB = sbase + 2*STAGE + p*STAGE;

        #pragma unroll
        for (int s = 0; s < 4; s++) {
            uint32_t csw = (uint32_t)(((s*2 + hh) ^ xr) << 4);
            uint32_t a[4][4], br[2][4];
            #pragma unroll
            for (int mt = 0; mt < 4; mt++)
                LDSM4(a[mt][0], a[mt][1], a[mt][2], a[mt][3], sA + aoff[mt] + csw);
            #pragma unroll
            for (int np = 0; np < 2; np++)
                LDSM4(br[np][0], br[np][1], br[np][2], br[np][3], sB + boff[np] + csw);
            #pragma unroll
            for (int mt = 0; mt < 4; mt++) {
                #pragma unroll
                for (int np = 0; np < 2; np++) {
                    mma_f16(d[mt][2*np + 0], a[mt], br[np][0], br[np][2]);
                    mma_f16(d[mt][2*np + 1], a[mt], br[np][1], br[np][3]);
                }
            }
        }
        __syncthreads();
    }
    #undef ISSUE

    // fused negative epilogue (accum layout: c0=(g,2tig) c1=(g,2tig+1) c2=(g+8,2tig) c3=(g+8,2tig+1))
    #pragma unroll
    for (int mt = 0; mt < 4; mt++) {
        #pragma unroll
        for (int h = 0; h < 2; h++) {
            int row = warp_m*64 + mt*16 + h*8 + g;
            int blb = slab[row];
            float alls = 0.f, hards = 0.f; int hc = 0;
            #pragma unroll
            for (int nt = 0; nt < 4; nt++) {
                #pragma unroll
                for (int e = 0; e < 2; e++) {
                    int col = warp_n*32 + nt*8 + tig*2 + e;
                    int c = ncls[col];
                    if (c >= 0 && c != blb) {
                        float sim = d[mt][nt][h*2 + e] * (1.0f / TEMP);
                        alls += sim;
                        if (sim > MARGIN) { hards += sim; hc++; }
                    }
                }
            }
            alls  += __shfl_down_sync(0xffffffffu, alls,  2, 4);
            alls  += __shfl_down_sync(0xffffffffu, alls,  1, 4);
            hards += __shfl_down_sync(0xffffffffu, hards, 2, 4);
            hards += __shfl_down_sync(0xffffffffu, hards, 1, 4);
            hc    += __shfl_down_sync(0xffffffffu, hc,    2, 4);
            hc    += __shfl_down_sync(0xffffffffu, hc,    1, 4);
            if (tig == 0) {
                sh_all [warp_n][row] = alls;
                sh_hard[warp_n][row] = hards;
                sh_hc  [warp_n][row] = hc;
            }
        }
    }
    __syncthreads();
    if (tid < TM) {
        float A4 = 0.f, H4 = 0.f; int C4 = 0;
        #pragma unroll
        for (int wn = 0; wn < 4; wn++) {
            A4 += sh_all[wn][tid]; H4 += sh_hard[wn][tid]; C4 += sh_hc[wn][tid];
        }
        int gb = b0 + tid;
        g_all [ntile*B + gb] = A4;
        g_hard[ntile*B + gb] = H4;
        g_hcnt[ntile*B + gb] = C4;
    }
}

// ---------------- finalize ----------------
__global__ void k_final(float* __restrict__ out) {
    int b = threadIdx.x;
    float alls = 0.f, hards = 0.f; int hc = 0;
    for (int t = 0; t < NT; t++) {
        alls  += g_all [t*B + b];
        hards += g_hard[t*B + b];
        hc    += g_hcnt[t*B + b];
    }
    float pos_sum = g_posb[b] + g_own[b];
    float pos_cnt = (float)(g_cntb[b] + KP);
    float pos_loss = -pos_sum / pos_cnt;
    float neg_loss = (hc > 0) ? (hards / (float)(hc > 1 ? hc : 1))
                              : (alls / (float)((C-1) * KN));
    __shared__ float sm[B];
    sm[b] = pos_loss + neg_loss;
    __syncthreads();
    for (int s = 256; s; s >>= 1) {
        if (b < s) sm[b] += sm[b + s];
        __syncthreads();
    }
    if (b == 0) out[0] = sm[0] / (float)B;
}

// ---------------- launch ----------------
extern "C" void kernel_launch(void* const* d_in, const int* in_sizes, int n_in,
                              void* d_out, int out_size) {
    const float* features   = (const float*)d_in[0];
    const int*   labels     = (const int*)  d_in[1];
    const float* memorybank = (const float*)d_in[2];
    const int*   memoryptr  = (const int*)  d_in[3];
    float* out = (float*)d_out;

    static int configured = 0;
    if (!configured) {
        cudaFuncSetAttribute(k_gemm, cudaFuncAttributeMaxDynamicSharedMemorySize, DYN_BYTES);
        configured = 1;
    }

    k_norm    <<<B, 256>>>(features);
    k_meta    <<<1, B>>>(labels, memoryptr);
    k_prepB   <<<NPAD, 128>>>(memorybank);
    k_batchpos<<<B, 256>>>(labels);
    k_own     <<<B, 256>>>(labels, memorybank);
    k_gemm    <<<dim3(NT, B/TM), 256, DYN_BYTES>>>(labels);
    k_final   <<<1, B>>>(out);
}

// round 16
// speedup vs baseline: 6.4022x; 1.2418x over previous
#include <cuda_runtime.h>
#include <cuda_fp16.h>
#include <math.h>
#include <stdint.h>

#define B 512
#define D 512
#define C 1000
#define M 200
#define KP 50
#define KN 20
#define NROWS (C*KN)              // 20000
#define TEMP 0.07f
#define MARGIN 0.5f
#define TM 128
#define TN 128
#define BK 64                     // halves per chunk (128B rows)
#define NCH (D/BK)                // 8
#define NT ((NROWS + TN - 1)/TN)  // 157
#define NPAD (NT*TN)              // 20096
#define STAGE (TM*128)            // 16384 bytes per stage buffer
#define NSTG 3
#define DYN_BYTES (2*NSTG*STAGE)  // A0..A2 B0..B2 = 96KB

// ---------------- PTX helpers ----------------
__device__ __forceinline__ uint32_t smem_u32(const void* p) {
    uint32_t a;
    asm("{ .reg .u64 t; cvta.to.shared.u64 t, %1; cvt.u32.u64 %0, t; }" : "=r"(a) : "l"(p));
    return a;
}
#define CP_ASYNC16(dst, src) \
    asm volatile("cp.async.cg.shared.global [%0], [%1], 16;" :: "r"(dst), "l"(src))
#define CP_COMMIT() asm volatile("cp.async.commit_group;" ::: "memory")
#define CP_WAIT1()  asm volatile("cp.async.wait_group 1;" ::: "memory")
#define CP_WAIT0()  asm volatile("cp.async.wait_group 0;" ::: "memory")

#define LDSM4(r0, r1, r2, r3, addr) \
    asm volatile("ldmatrix.sync.aligned.m8n8.x4.shared.b16 {%0,%1,%2,%3}, [%4];" \
        : "=r"(r0), "=r"(r1), "=r"(r2), "=r"(r3) : "r"(addr))

__device__ __forceinline__ void mma_f16(float* d, const uint32_t* a, uint32_t b0, uint32_t b1) {
    asm volatile(
        "mma.sync.aligned.m16n8k16.row.col.f32.f16.f16.f32 "
        "{%0,%1,%2,%3}, {%4,%5,%6,%7}, {%8,%9}, {%0,%1,%2,%3};"
        : "+f"(d[0]), "+f"(d[1]), "+f"(d[2]), "+f"(d[3])
        : "r"(a[0]), "r"(a[1]), "r"(a[2]), "r"(a[3]), "r"(b0), "r"(b1));
}

// ---------------- scratch ----------------
__device__ float  g_f[B*D];                  // normalized features (fp32, exact paths)
__device__ __half g_ah[B*D];                 // fp16 A
__device__ __half g_bh[(size_t)NPAD*D];      // fp16 B, gather-resolved
__device__ int   g_rank[B];
__device__ int   g_gsize[B];
__device__ int   g_fidx[B];
__device__ int   g_ov[C*KP];
__device__ float g_own[B];
__device__ float g_posb[B];
__device__ int   g_cntb[B];
__device__ float g_all [NT*B];
__device__ float g_hard[NT*B];
__device__ int   g_hcnt[NT*B];

// ---------------- normalize (+ emit fp16 A) ----------------
__global__ void k_norm(const float* __restrict__ x) {
    int r = blockIdx.x, t = threadIdx.x;
    __shared__ float red[8];
    __shared__ float inv_s;
    const float* row = x + (size_t)r * D;
    float s = 0.f;
    for (int d = t; d < D; d += 256) { float v = row[d]; s = fmaf(v, v, s); }
    for (int o = 16; o; o >>= 1) s += __shfl_down_sync(0xffffffffu, s, o);
    if ((t & 31) == 0) red[t >> 5] = s;
    __syncthreads();
    if (t == 0) {
        float tot = 0.f;
        for (int i = 0; i < 8; i++) tot += red[i];
        inv_s = 1.0f / fmaxf(sqrtf(tot), 1e-12f);
    }
    __syncthreads();
    float inv = inv_s;
    for (int d = t; d < D; d += 256) {
        float v = row[d] * inv;
        g_f[(size_t)r * D + d] = v;
        g_ah[(size_t)r * D + d] = __float2half_rn(v);
    }
}

// ---------------- meta ----------------
__global__ void k_meta(const int* __restrict__ lab, const int* __restrict__ ptr) {
    __shared__ int sl[B];
    int i = threadIdx.x;
    for (int j = i; j < C*KP; j += B) g_ov[j] = -1;
    sl[i] = lab[i];
    __syncthreads();
    int li = sl[i];
    int cb = 0, tot = 0, first = B;
    for (int j = 0; j < B; j++) {
        if (sl[j] == li) { tot++; if (j < i) cb++; if (j < first) first = j; }
    }
    g_rank[i] = cb; g_gsize[i] = tot; g_fidx[i] = first;
    int wp = (ptr[li] + cb) % M;
    if (wp < KP) atomicMax(&g_ov[li*KP + wp], i);
}

// ---------------- prep B: resolve gather, fp16-round ----------------
__global__ void k_prepB(const float* __restrict__ mb) {
    int n = blockIdx.x, t = threadIdx.x;
    __half* dst = g_bh + (size_t)n*D + t*4;
    if (n >= NROWS) {
        *(uint2*)dst = make_uint2(0u, 0u);
        return;
    }
    int c = n / KN, k = n - c*KN;
    int o = g_ov[c*KP + k];
    const float* src = (o >= 0) ? (g_f + (size_t)o*D) : (mb + ((size_t)c*M + k)*D);
    float4 v = *(const float4*)(src + t*4);
    __half2 h01 = __floats2half2_rn(v.x, v.y);
    __half2 h23 = __floats2half2_rn(v.z, v.w);
    uint2 out;
    out.x = *(uint32_t*)&h01;
    out.y = *(uint32_t*)&h23;
    *(uint2*)dst = out;
}

// ---------------- positives: own-class memory (exact) + in-batch (exact) ----------------
__global__ void k_pos(const int* __restrict__ lab, const float* __restrict__ mb) {
    int b = blockIdx.x, t = threadIdx.x;
    int lane = t & 31, w = t >> 5;
    __shared__ float fb[D];
    __shared__ int sl[B];
    for (int d = t; d < D; d += 256) fb[d] = g_f[(size_t)b*D + d];
    for (int j = t; j < B; j += 256) sl[j] = lab[j];
    __syncthreads();
    int c = lab[b];

    // own-class: 50 memory dots
    float acc = 0.f;
    for (int k = w; k < KP; k += 8) {
        int o = g_ov[c*KP + k];
        const float* row = (o >= 0) ? (g_f + (size_t)o * D)
                                    : (mb + ((size_t)c * M + k) * D);
        float s = 0.f;
        for (int d = lane; d < D; d += 32) s = fmaf(fb[d], row[d], s);
        for (int off = 16; off; off >>= 1) s += __shfl_down_sync(0xffffffffu, s, off);
        if (!lane) acc += s / TEMP;
    }

    // in-batch positives
    float bs = 0.f; int bc = 0;
    if (g_gsize[b] > 1) {
        int fi = g_fidx[b];
        for (int j = w; j < B; j += 8) {
            if (sl[j] == c && g_rank[j] != fi) {
                const float* fj = g_f + (size_t)j * D;
                float d0 = 0.f;
                for (int d = lane; d < D; d += 32) d0 = fmaf(fb[d], fj[d], d0);
                for (int o = 16; o; o >>= 1) d0 += __shfl_down_sync(0xffffffffu, d0, o);
                if (!lane) { bs += d0 / TEMP; bc++; }
            }
        }
    }

    __shared__ float ws[8], ss[8]; __shared__ int cs[8];
    if (!lane) { ws[w] = acc; ss[w] = bs; cs[w] = bc; }
    __syncthreads();
    if (t == 0) {
        float S = 0.f, S2 = 0.f; int CC = 0;
        for (int i = 0; i < 8; i++) { S += ws[i]; S2 += ss[i]; CC += cs[i]; }
        g_own[b] = S; g_posb[b] = S2; g_cntb[b] = CC;
    }
}

// ---------------- main GEMM: fp16 mma.sync + ldmatrix, 3-stage cp.async ----------------
__global__ __launch_bounds__(256, 2) void k_gemm(const int* __restrict__ lab) {
    extern __shared__ char dsm[];
    __shared__ int ncls[TN];
    __shared__ int slab[TM];
    __shared__ float sh_all[4][TM];
    __shared__ float sh_hard[4][TM];
    __shared__ int   sh_hc[4][TM];

    int tid = threadIdx.x, wid = tid >> 5, lid = tid & 31;
    int g = lid >> 2, tig = lid & 3;
    int warp_m = wid & 1, warp_n = wid >> 1;
    int ntile = blockIdx.x, btile = blockIdx.y;
    int n0 = ntile * TN, b0 = btile * TM;

    uint32_t sbase = smem_u32(dsm);

    for (int i = tid; i < TN; i += 256) {
        int n = n0 + i;
        ncls[i] = (n < NROWS) ? (n / KN) : -1;
    }
    for (int i = tid; i < TM; i += 256) slab[i] = lab[b0 + i];

    float d[4][4][4];
    #pragma unroll
    for (int mt = 0; mt < 4; mt++)
        #pragma unroll
        for (int nt = 0; nt < 4; nt++)
            #pragma unroll
            for (int e = 0; e < 4; e++) d[mt][nt][e] = 0.f;

    int cp_r[4], cp_c[4];
    #pragma unroll
    for (int it = 0; it < 4; it++) { int i = tid + it*256; cp_r[it] = i >> 3; cp_c[it] = i & 7; }

    #define ISSUE(ch, q) do { \
        uint32_t abase_ = sbase + (q)*STAGE; \
        uint32_t bbase_ = sbase + NSTG*STAGE + (q)*STAGE; \
        int kb_ = (ch)*BK; \
        _Pragma("unroll") \
        for (int it = 0; it < 4; it++) { \
            int r_ = cp_r[it], c_ = cp_c[it]; \
            int sc_ = c_ ^ (r_ & 7); \
            CP_ASYNC16(abase_ + (uint32_t)(r_*128 + sc_*16), \
                       g_ah + (size_t)(b0 + r_)*D + kb_ + c_*8); \
            CP_ASYNC16(bbase_ + (uint32_t)(r_*128 + sc_*16), \
                       g_bh + (size_t)(n0 + r_)*D + kb_ + c_*8); \
        } \
        CP_COMMIT(); \
    } while (0)

    ISSUE(0, 0);
    ISSUE(1, 1);

    int xr = lid & 7;
    int jrow = (lid >> 3) & 1;
    int hh = lid >> 4;
    uint32_t aoff[4], boff[2];
    #pragma unroll
    for (int mt = 0; mt < 4; mt++)
        aoff[mt] = (uint32_t)((warp_m*64 + mt*16 + jrow*8 + xr) * 128);
    #pragma unroll
    for (int np = 0; np < 2; np++)
        boff[np] = (uint32_t)((warp_n*32 + np*16 + jrow*8 + xr) * 128);

    int stg = 0;
    for (int ch = 0; ch < NCH; ch++) {
        if (ch + 1 < NCH) CP_WAIT1(); else CP_WAIT0();
        __syncthreads();

        uint32_t sA = sbase + stg*STAGE;
        uint32_t sB = sbase + NSTG*STAGE + stg*STAGE;

        #pragma unroll
        for (int s = 0; s < 4; s++) {
            uint32_t csw = (uint32_t)(((s*2 + hh) ^ xr) << 4);
            uint32_t a[4][4], br[2][4];
            #pragma unroll
            for (int mt = 0; mt < 4; mt++)
                LDSM4(a[mt][0], a[mt][1], a[mt][2], a[mt][3], sA + aoff[mt] + csw);
            #pragma unroll
            for (int np = 0; np < 2; np++)
                LDSM4(br[np][0], br[np][1], br[np][2], br[np][3], sB + boff[np] + csw);
            #pragma unroll
            for (int mt = 0; mt < 4; mt++) {
                #pragma unroll
                for (int np = 0; np < 2; np++) {
                    mma_f16(d[mt][2*np + 0], a[mt], br[np][0], br[np][2]);
                    mma_f16(d[mt][2*np + 1], a[mt], br[np][1], br[np][3]);
                }
            }
        }
        __syncthreads();
        if (ch + 2 < NCH) {
            int q = stg + 2; if (q >= NSTG) q -= NSTG;
            ISSUE(ch + 2, q);
        }
        if (++stg == NSTG) stg = 0;
    }
    #undef ISSUE

    // fused negative epilogue
    #pragma unroll
    for (int mt = 0; mt < 4; mt++) {
        #pragma unroll
        for (int h = 0; h < 2; h++) {
            int row = warp_m*64 + mt*16 + h*8 + g;
            int blb = slab[row];
            float alls = 0.f, hards = 0.f; int hc = 0;
            #pragma unroll
            for (int nt = 0; nt < 4; nt++) {
                #pragma unroll
                for (int e = 0; e < 2; e++) {
                    int col = warp_n*32 + nt*8 + tig*2 + e;
                    int c = ncls[col];
                    if (c >= 0 && c != blb) {
                        float sim = d[mt][nt][h*2 + e] * (1.0f / TEMP);
                        alls += sim;
                        if (sim > MARGIN) { hards += sim; hc++; }
                    }
                }
            }
            alls  += __shfl_down_sync(0xffffffffu, alls,  2, 4);
            alls  += __shfl_down_sync(0xffffffffu, alls,  1, 4);
            hards += __shfl_down_sync(0xffffffffu, hards, 2, 4);
            hards += __shfl_down_sync(0xffffffffu, hards, 1, 4);
            hc    += __shfl_down_sync(0xffffffffu, hc,    2, 4);
            hc    += __shfl_down_sync(0xffffffffu, hc,    1, 4);
            if (tig == 0) {
                sh_all [warp_n][row] = alls;
                sh_hard[warp_n][row] = hards;
                sh_hc  [warp_n][row] = hc;
            }
        }
    }
    __syncthreads();
    if (tid < TM) {
        float A4 = 0.f, H4 = 0.f; int C4 = 0;
        #pragma unroll
        for (int wn = 0; wn < 4; wn++) {
            A4 += sh_all[wn][tid]; H4 += sh_hard[wn][tid]; C4 += sh_hc[wn][tid];
        }
        int gb = b0 + tid;
        g_all [ntile*B + gb] = A4;
        g_hard[ntile*B + gb] = H4;
        g_hcnt[ntile*B + gb] = C4;
    }
}

// ---------------- finalize ----------------
__global__ void k_final(float* __restrict__ out) {
    int b = threadIdx.x;
    float alls = 0.f, hards = 0.f; int hc = 0;
    for (int t = 0; t < NT; t++) {
        alls  += g_all [t*B + b];
        hards += g_hard[t*B + b];
        hc    += g_hcnt[t*B + b];
    }
    float pos_sum = g_posb[b] + g_own[b];
    float pos_cnt = (float)(g_cntb[b] + KP);
    float pos_loss = -pos_sum / pos_cnt;
    float neg_loss = (hc > 0) ? (hards / (float)(hc > 1 ? hc : 1))
                              : (alls / (float)((C-1) * KN));
    __shared__ float sm[B];
    sm[b] = pos_loss + neg_loss;
    __syncthreads();
    for (int s = 256; s; s >>= 1) {
        if (b < s) sm[b] += sm[b + s];
        __syncthreads();
    }
    if (b == 0) out[0] = sm[0] / (float)B;
}

// ---------------- launch ----------------
extern "C" void kernel_launch(void* const* d_in, const int* in_sizes, int n_in,
                              void* d_out, int out_size) {
    const float* features   = (const float*)d_in[0];
    const int*   labels     = (const int*)  d_in[1];
    const float* memorybank = (const float*)d_in[2];
    const int*   memoryptr  = (const int*)  d_in[3];
    float* out = (float*)d_out;

    static cudaStream_t s1 = nullptr;
    static cudaEvent_t evFork = nullptr, evJoin = nullptr;
    static int configured = 0;
    if (!configured) {
        cudaFuncSetAttribute(k_gemm, cudaFuncAttributeMaxDynamicSharedMemorySize, DYN_BYTES);
        cudaStreamCreateWithFlags(&s1, cudaStreamNonBlocking);
        cudaEventCreateWithFlags(&evFork, cudaEventDisableTiming);
        cudaEventCreateWithFlags(&evJoin, cudaEventDisableTiming);
        configured = 1;
    }

    k_norm <<<B, 256>>>(features);
    k_meta <<<1, B>>>(labels, memoryptr);

    // fork: positives run concurrently with prepB+gemm
    cudaEventRecord(evFork, 0);
    cudaStreamWaitEvent(s1, evFork, 0);
    k_pos  <<<B, 256, 0, s1>>>(labels, memorybank);
    cudaEventRecord(evJoin, s1);

    k_prepB<<<NPAD, 128>>>(memorybank);
    k_gemm <<<dim3(NT, B/TM), 256, DYN_BYTES>>>(labels);

    cudaStreamWaitEvent(0, evJoin, 0);
    k_final<<<1, B>>>(out);
}